// round 1
// baseline (speedup 1.0000x reference)
#include <cuda_runtime.h>
#include <cstdint>

// ---------------------------------------------------------------------------
// Neck: 3 x (modulated deformable 3x3 conv  ->  ConvTranspose2d(k3,s2,p1,op1))
// Implemented as im2col + tiled SGEMM for every conv.
// All scratch in __device__ globals (no allocations allowed).
// ---------------------------------------------------------------------------

#define BATCH 8

// max col: tconv stage3: K=64*9=576, N=8*256*256=524288 -> 301,989,888 floats
__device__ float g_col[301989888];
// Y (deform-conv outputs): max 8*64*128*128 = 8,388,608
__device__ float g_bufA[8388608];
// X (tconv outputs): max 8*128*128*128 = 16,777,216
__device__ float g_bufB[16777216];
// raw offset conv output [B,18,H,W], max 8*18*128*128
__device__ float g_off[2359296];
// raw mod conv output [B,9,H,W]
__device__ float g_mod[1179648];
// transposed tconv weights [Cout,Cin,3,3], max 256*256*9
__device__ float g_wtt[589824];

// ---------------------------------------------------------------------------
// im2col for regular 3x3 conv, pad 1.  col[(c*9+t)][n], n = b*H*W + h*W + w
// ---------------------------------------------------------------------------
__global__ void im2col3x3(const float* __restrict__ x, float* __restrict__ col,
                          int C, int H, int W, int N) {
    int idx = blockIdx.x * blockDim.x + threadIdx.x;
    int total = C * N;
    if (idx >= total) return;
    int n = idx % N;
    int c = idx / N;
    int HW = H * W;
    int hw = n % HW;
    int b  = n / HW;
    int h = hw / W, w = hw % W;
    const float* xp = x + ((size_t)(b * C + c)) * HW;
    size_t outBase = ((size_t)c * 9) * (size_t)N + n;
#pragma unroll
    for (int t = 0; t < 9; t++) {
        int iy = h + t / 3 - 1;
        int ix = w + t % 3 - 1;
        float v = 0.f;
        if (iy >= 0 && iy < H && ix >= 0 && ix < W) v = xp[iy * W + ix];
        col[outBase + (size_t)t * N] = v;
    }
}

// ---------------------------------------------------------------------------
// Deformable im2col: col[(c*9+k)][n] = bilinear(x, py, px) * sigmoid(mod)
// off: [B,18,H,W] (dy,dx interleaved per tap), mod: [B,9,H,W]
// ---------------------------------------------------------------------------
__global__ void deform_im2col(const float* __restrict__ x,
                              const float* __restrict__ off,
                              const float* __restrict__ modr,
                              float* __restrict__ col,
                              int C, int H, int W, int N) {
    int idx = blockIdx.x * blockDim.x + threadIdx.x;
    int total = 9 * N;
    if (idx >= total) return;
    int n = idx % N;
    int k = idx / N;
    int HW = H * W;
    int hw = n % HW;
    int b  = n / HW;
    int h = hw / W, w = hw % W;

    float dy = off[((size_t)(b * 18 + 2 * k)) * HW + hw];
    float dx = off[((size_t)(b * 18 + 2 * k + 1)) * HW + hw];
    float mr = modr[((size_t)(b * 9 + k)) * HW + hw];
    float m  = 1.f / (1.f + expf(-mr));

    float py = dy + (float)(k / 3 - 1) + (float)h;
    float px = dx + (float)(k % 3 - 1) + (float)w;

    float y0f = floorf(py), x0f = floorf(px);
    float wy = py - y0f, wx = px - x0f;
    int y0 = (int)y0f, x0 = (int)x0f;
    int y1 = y0 + 1,   x1 = x0 + 1;

    bool vy0 = (y0 >= 0) && (y0 <= H - 1);
    bool vy1 = (y1 >= 0) && (y1 <= H - 1);
    bool vx0 = (x0 >= 0) && (x0 <= W - 1);
    bool vx1 = (x1 >= 0) && (x1 <= W - 1);

    int y0c = min(max(y0, 0), H - 1);
    int y1c = min(max(y1, 0), H - 1);
    int x0c = min(max(x0, 0), W - 1);
    int x1c = min(max(x1, 0), W - 1);

    float w00 = (1.f - wy) * (1.f - wx) * ((vy0 && vx0) ? m : 0.f);
    float w01 = (1.f - wy) * wx         * ((vy0 && vx1) ? m : 0.f);
    float w10 = wy * (1.f - wx)         * ((vy1 && vx0) ? m : 0.f);
    float w11 = wy * wx                 * ((vy1 && vx1) ? m : 0.f);

    int i00 = y0c * W + x0c;
    int i01 = y0c * W + x1c;
    int i10 = y1c * W + x0c;
    int i11 = y1c * W + x1c;

    const float* xb = x + (size_t)b * C * HW;
    size_t ob = (size_t)k * N + n;
    for (int c = 0; c < C; c++) {
        const float* xc = xb + (size_t)c * HW;
        float v = w00 * xc[i00] + w01 * xc[i01] + w10 * xc[i10] + w11 * xc[i11];
        col[ob + (size_t)c * 9 * (size_t)N] = v;
    }
}

// ---------------------------------------------------------------------------
// im2col for ConvTranspose2d(k3, s2, p1, op1) in gather form:
// out[oy,ox] = sum_{cin,ky,kx} in[(oy+1-ky)/2, (ox+1-kx)/2] * w[cin,cout,ky,kx]
// col[(c*9+t)][n], n over B*(2H)*(2W)
// ---------------------------------------------------------------------------
__global__ void tconv_im2col(const float* __restrict__ in, float* __restrict__ col,
                             int C, int H, int W, int Nout) {
    int idx = blockIdx.x * blockDim.x + threadIdx.x;
    int total = C * Nout;
    if (idx >= total) return;
    int n = idx % Nout;
    int c = idx / Nout;
    int OH = 2 * H, OW = 2 * W;
    int OHW = OH * OW;
    int ohw = n % OHW;
    int b   = n / OHW;
    int oy = ohw / OW, ox = ohw % OW;
    const float* ip = in + ((size_t)(b * C + c)) * H * W;
    size_t outBase = ((size_t)c * 9) * (size_t)Nout + n;
#pragma unroll
    for (int t = 0; t < 9; t++) {
        int ky = t / 3, kx = t % 3;
        int ny = oy + 1 - ky;
        int nx = ox + 1 - kx;
        float v = 0.f;
        if (((ny & 1) == 0) && ((nx & 1) == 0)) {
            int iy = ny >> 1, ix = nx >> 1;
            if (iy >= 0 && iy < H && ix >= 0 && ix < W) v = ip[iy * W + ix];
        }
        col[outBase + (size_t)t * Nout] = v;
    }
}

// ---------------------------------------------------------------------------
// transpose tconv weights: [Cin, Cout, 3, 3] -> [Cout, Cin, 3, 3]
// ---------------------------------------------------------------------------
__global__ void transpose_wt(const float* __restrict__ wt, float* __restrict__ wtt,
                             int Cin, int Cout) {
    int idx = blockIdx.x * blockDim.x + threadIdx.x;
    int total = Cin * Cout * 9;
    if (idx >= total) return;
    int t = idx % 9;
    int r = idx / 9;
    int o = r % Cout;
    int c = r / Cout;
    wtt[((size_t)(o * Cin + c)) * 9 + t] = wt[((size_t)(c * Cout + o)) * 9 + t];
}

// ---------------------------------------------------------------------------
// Tiled SGEMM: C = A[M,K] * B[K,N] + bias[M], output written NCHW:
//   n = b*HW + hw  ->  out[((b*M + m)*HW) + hw]
// BM=BN=128, BK=8, 256 threads, 8x8 register microtile.
// Requires: K % 8 == 0, N % 128 == 0 (always true here). M arbitrary.
// ---------------------------------------------------------------------------
__global__ __launch_bounds__(256) void sgemm(
        const float* __restrict__ A, const float* __restrict__ B,
        const float* __restrict__ bias, float* __restrict__ C,
        int M, int K, int N, int HW) {
    const int BM = 128, BN = 128, BK = 8, TM = 8, TN = 8;
    __shared__ float As[BK][BM];
    __shared__ float Bs[BK][BN];

    int tid = threadIdx.x;
    int mBase = blockIdx.y * BM;
    int nBase = blockIdx.x * BN;

    int aRow = tid >> 1;          // 0..127
    int aCol = (tid & 1) << 2;    // 0 or 4
    int bRow = tid >> 5;          // 0..7
    int bCol = (tid & 31) << 2;   // 0..124

    int ty = tid >> 4;            // 0..15
    int tx = tid & 15;            // 0..15

    float acc[TM][TN];
#pragma unroll
    for (int i = 0; i < TM; i++)
#pragma unroll
        for (int j = 0; j < TN; j++) acc[i][j] = 0.f;

    for (int k0 = 0; k0 < K; k0 += BK) {
        float4 av = make_float4(0.f, 0.f, 0.f, 0.f);
        int gm = mBase + aRow;
        if (gm < M)
            av = *reinterpret_cast<const float4*>(&A[(size_t)gm * K + k0 + aCol]);
        As[aCol + 0][aRow] = av.x;
        As[aCol + 1][aRow] = av.y;
        As[aCol + 2][aRow] = av.z;
        As[aCol + 3][aRow] = av.w;

        float4 bv = *reinterpret_cast<const float4*>(
            &B[(size_t)(k0 + bRow) * (size_t)N + nBase + bCol]);
        *reinterpret_cast<float4*>(&Bs[bRow][bCol]) = bv;

        __syncthreads();

#pragma unroll
        for (int kk = 0; kk < BK; kk++) {
            float ar[TM], br[TN];
#pragma unroll
            for (int i = 0; i < TM; i++) ar[i] = As[kk][ty * TM + i];
#pragma unroll
            for (int j = 0; j < TN; j++) br[j] = Bs[kk][tx * TN + j];
#pragma unroll
            for (int i = 0; i < TM; i++)
#pragma unroll
                for (int j = 0; j < TN; j++)
                    acc[i][j] += ar[i] * br[j];
        }
        __syncthreads();
    }

#pragma unroll
    for (int i = 0; i < TM; i++) {
        int m = mBase + ty * TM + i;
        if (m >= M) continue;
        float bvl = bias[m];
#pragma unroll
        for (int j = 0; j < TN; j++) {
            int n = nBase + tx * TN + j;   // n < N guaranteed (N % 128 == 0)
            int b = n / HW;
            int hw = n - b * HW;
            C[((size_t)(b * M + m)) * HW + hw] = acc[i][j] + bvl;
        }
    }
}

// ---------------------------------------------------------------------------

static inline float* symaddr(const void* sym) {
    void* p = nullptr;
    cudaGetSymbolAddress(&p, sym);
    return (float*)p;
}

extern "C" void kernel_launch(void* const* d_in, const int* in_sizes, int n_in,
                              void* d_out, int out_size) {
    float* col  = symaddr(g_col);
    float* bufA = symaddr(g_bufA);
    float* bufB = symaddr(g_bufB);
    float* offb = symaddr(g_off);
    float* modb = symaddr(g_mod);
    float* wtt  = symaddr(g_wtt);

    struct Stage {
        const float *w_off, *b_off, *w_mod, *b_mod, *w, *b, *wt, *bt;
        int C, H, W, O;
    };
    Stage st[3];
    for (int i = 0; i < 3; i++) {
        int base = 1 + i * 8;
        st[i].w_off = (const float*)d_in[base + 0];
        st[i].b_off = (const float*)d_in[base + 1];
        st[i].w_mod = (const float*)d_in[base + 2];
        st[i].b_mod = (const float*)d_in[base + 3];
        st[i].w     = (const float*)d_in[base + 4];
        st[i].b     = (const float*)d_in[base + 5];
        st[i].wt    = (const float*)d_in[base + 6];
        st[i].bt    = (const float*)d_in[base + 7];
    }
    st[0].C = 512; st[0].H = 32;  st[0].W = 32;  st[0].O = 256;
    st[1].C = 256; st[1].H = 64;  st[1].W = 64;  st[1].O = 128;
    st[2].C = 128; st[2].H = 128; st[2].W = 128; st[2].O = 64;

    const float* X = (const float*)d_in[0];

    for (int i = 0; i < 3; i++) {
        int C = st[i].C, H = st[i].H, W = st[i].W, O = st[i].O;
        int HW = H * W;
        int N = BATCH * HW;
        int K = C * 9;

        // 1) regular im2col of X for offset/mod convs
        {
            int total = C * N;
            im2col3x3<<<(total + 255) / 256, 256>>>(X, col, C, H, W, N);
        }
        // 2) offset conv (M=18) and mod conv (M=9)
        {
            dim3 g((N + 127) / 128, 1);
            sgemm<<<g, 256>>>(st[i].w_off, col, st[i].b_off, offb, 18, K, N, HW);
            sgemm<<<g, 256>>>(st[i].w_mod, col, st[i].b_mod, modb, 9, K, N, HW);
        }
        // 3) deformable im2col (bilinear sample * sigmoid(mod))
        {
            int total = 9 * N;
            deform_im2col<<<(total + 255) / 256, 256>>>(X, offb, modb, col, C, H, W, N);
        }
        // 4) main deform conv GEMM -> Y in bufA
        float* Y = bufA;
        {
            dim3 g((N + 127) / 128, (O + 127) / 128);
            sgemm<<<g, 256>>>(st[i].w, col, st[i].b, Y, O, K, N, HW);
        }
        // 5) transposed conv: weight transpose, gather im2col, GEMM
        {
            int total = O * O * 9;
            transpose_wt<<<(total + 255) / 256, 256>>>(st[i].wt, wtt, O, O);
        }
        int OH = 2 * H, OW = 2 * W;
        int Nout = BATCH * OH * OW;
        {
            int total = O * Nout;
            tconv_im2col<<<(total + 255) / 256, 256>>>(Y, col, O, H, W, Nout);
        }
        float* Xn = (i == 2) ? (float*)d_out : bufB;
        {
            dim3 g((Nout + 127) / 128, (O + 127) / 128);
            sgemm<<<g, 256>>>(wtt, col, st[i].bt, Xn, O, O * 9, Nout, OH * OW);
        }
        X = Xn;
    }
}

// round 3
// speedup vs baseline: 1.9562x; 1.9562x over previous
#include <cuda_runtime.h>
#include <cstdint>

// ---------------------------------------------------------------------------
// Neck: 3 x (modulated deformable 3x3 conv -> ConvTranspose2d(k3,s2,p1,op1))
//  - off/mod convs: single fused-im2col GEMM, M=27
//  - deform conv:   deform_im2col -> tiled SGEMM
//  - tconv:         parity-decomposed (4 classes), im2col fused into GEMM
// ---------------------------------------------------------------------------

#define BATCH 8

__device__ float g_col[150994944];   // deform col: max K=1152 x N=131072
__device__ float g_bufA[8388608];    // deform outputs Y
__device__ float g_bufB[16777216];   // tconv outputs
__device__ float g_offmod[3538944];  // [B,27,HW] combined off+mod conv out
__device__ float g_wom[124416];      // [27, C*9] combined off/mod weights
__device__ float g_bom[32];
__device__ float g_wtp[589824];      // parity tconv weights, total 9*O*O

// ---------------------------------------------------------------------------
__global__ void build_wom(const float* __restrict__ w_off, const float* __restrict__ b_off,
                          const float* __restrict__ w_mod, const float* __restrict__ b_mod,
                          float* __restrict__ wom, float* __restrict__ bom, int K) {
    int idx = blockIdx.x * blockDim.x + threadIdx.x;
    int total = 27 * K;
    if (idx < 27) bom[idx] = (idx < 18) ? b_off[idx] : b_mod[idx - 18];
    if (idx >= total) return;
    int m = idx / K;
    int k = idx - m * K;
    wom[idx] = (m < 18) ? w_off[(size_t)m * K + k] : w_mod[(size_t)(m - 18) * K + k];
}

// A_p[o][c*nt + t] = wt[c, o, ky(t), kx(t)];  wt layout [Cin=O, Cout=O, 3, 3]
__global__ void build_wtp(const float* __restrict__ wt, float* __restrict__ out,
                          int O, int nt, int ry, int rx) {
    int idx = blockIdx.x * blockDim.x + threadIdx.x;
    int total = O * O * nt;
    if (idx >= total) return;
    int o = idx / (O * nt);
    int r = idx - o * (O * nt);
    int c = r / nt;
    int t = r - c * nt;
    int ntx = rx + 1;
    int tyi = t / ntx;
    int txi = t - tyi * ntx;
    int ky = ry ? (tyi == 0 ? 0 : 2) : 1;
    int kx = rx ? (txi == 0 ? 0 : 2) : 1;
    out[idx] = wt[((size_t)(c * O + o)) * 9 + ky * 3 + kx];
}

// ---------------------------------------------------------------------------
__global__ void deform_im2col(const float* __restrict__ x,
                              const float* __restrict__ om,
                              float* __restrict__ col,
                              int C, int H, int W, int N) {
    int idx = blockIdx.x * blockDim.x + threadIdx.x;
    int total = 9 * N;
    if (idx >= total) return;
    int n = idx % N;
    int k = idx / N;
    int HW = H * W;
    int hw = n % HW;
    int b  = n / HW;
    int h = hw / W, w = hw % W;

    float dy = om[((size_t)(b * 27 + 2 * k)) * HW + hw];
    float dx = om[((size_t)(b * 27 + 2 * k + 1)) * HW + hw];
    float mr = om[((size_t)(b * 27 + 18 + k)) * HW + hw];
    float m  = 1.f / (1.f + expf(-mr));

    float py = dy + (float)(k / 3 - 1) + (float)h;
    float px = dx + (float)(k % 3 - 1) + (float)w;

    float y0f = floorf(py), x0f = floorf(px);
    float wy = py - y0f, wx = px - x0f;
    int y0 = (int)y0f, x0 = (int)x0f;
    int y1 = y0 + 1,   x1 = x0 + 1;

    bool vy0 = (y0 >= 0) && (y0 <= H - 1);
    bool vy1 = (y1 >= 0) && (y1 <= H - 1);
    bool vx0 = (x0 >= 0) && (x0 <= W - 1);
    bool vx1 = (x1 >= 0) && (x1 <= W - 1);

    int y0c = min(max(y0, 0), H - 1);
    int y1c = min(max(y1, 0), H - 1);
    int x0c = min(max(x0, 0), W - 1);
    int x1c = min(max(x1, 0), W - 1);

    float w00 = (1.f - wy) * (1.f - wx) * ((vy0 && vx0) ? m : 0.f);
    float w01 = (1.f - wy) * wx         * ((vy0 && vx1) ? m : 0.f);
    float w10 = wy * (1.f - wx)         * ((vy1 && vx0) ? m : 0.f);
    float w11 = wy * wx                 * ((vy1 && vx1) ? m : 0.f);

    int i00 = y0c * W + x0c;
    int i01 = y0c * W + x1c;
    int i10 = y1c * W + x0c;
    int i11 = y1c * W + x1c;

    const float* xb = x + (size_t)b * C * HW;
    size_t ob = (size_t)k * N + n;
    size_t stride = (size_t)9 * N;
    for (int c = 0; c < C; c++) {
        const float* xc = xb + (size_t)c * HW;
        float v = w00 * xc[i00] + w01 * xc[i01] + w10 * xc[i10] + w11 * xc[i11];
        col[ob + (size_t)c * stride] = v;
    }
}

// ---------------------------------------------------------------------------
// SGEMM inner microkernel (BN=128, BK=8, 256 threads, TN=8)
// ---------------------------------------------------------------------------
#define GEMM_INNER()                                                      \
    _Pragma("unroll")                                                     \
    for (int kk = 0; kk < 8; kk++) {                                      \
        float ar[TM], br[8];                                              \
        _Pragma("unroll")                                                 \
        for (int i = 0; i < TM; i++) ar[i] = As[kk][ty * TM + i];         \
        _Pragma("unroll")                                                 \
        for (int j = 0; j < 8; j++) br[j] = Bs[kk][tx * 8 + j];           \
        _Pragma("unroll")                                                 \
        for (int i = 0; i < TM; i++)                                      \
            _Pragma("unroll")                                             \
            for (int j = 0; j < 8; j++) acc[i][j] += ar[i] * br[j];       \
    }

// ---- col-based SGEMM (deform conv); out[((b*M+m)*HW)+hw] ----
template<int BM, int TM>
__global__ __launch_bounds__(256) void sgemm_col(
        const float* __restrict__ A, const float* __restrict__ B,
        const float* __restrict__ bias, float* __restrict__ C,
        int M, int K, int N, int HW) {
    __shared__ float As[8][BM];
    __shared__ float Bs[8][128];
    int tid = threadIdx.x;
    int mBase = blockIdx.y * BM;
    int nBase = blockIdx.x * 128;
    int bRow = tid >> 5, bCol = (tid & 31) << 2;
    int ty = tid >> 4, tx = tid & 15;

    float acc[TM][8] = {};
    for (int k0 = 0; k0 < K; k0 += 8) {
        constexpr int LA = BM * 8 / 256;
#pragma unroll
        for (int i = 0; i < LA; i++) {
            int e = tid + i * 256;
            int r = e >> 3, cc = e & 7;
            int gm = mBase + r;
            As[cc][r] = (gm < M) ? A[(size_t)gm * K + k0 + cc] : 0.f;
        }
        float4 bv = *reinterpret_cast<const float4*>(
            &B[(size_t)(k0 + bRow) * (size_t)N + nBase + bCol]);
        *reinterpret_cast<float4*>(&Bs[bRow][bCol]) = bv;
        __syncthreads();
        GEMM_INNER();
        __syncthreads();
    }
    int bI[8], hwI[8];
#pragma unroll
    for (int j = 0; j < 8; j++) {
        int n = nBase + tx * 8 + j;
        bI[j] = n / HW; hwI[j] = n - bI[j] * HW;
    }
#pragma unroll
    for (int i = 0; i < TM; i++) {
        int m = mBase + ty * TM + i;
        if (m >= M) continue;
        float bvl = bias[m];
#pragma unroll
        for (int j = 0; j < 8; j++)
            C[((size_t)(bI[j] * M + m)) * HW + hwI[j]] = acc[i][j] + bvl;
    }
}

// ---- fused 3x3-conv SGEMM (off/mod convs) ----
template<int BM, int TM>
__global__ __launch_bounds__(256) void sgemm_c3x3(
        const float* __restrict__ A, const float* __restrict__ X,
        const float* __restrict__ bias, float* __restrict__ Out,
        int M, int C, int K, int N, int H, int W) {
    __shared__ float As[8][BM];
    __shared__ float Bs[8][128];
    int tid = threadIdx.x;
    int mBase = blockIdx.y * BM;
    int nBase = blockIdx.x * 128;
    int bRow = tid >> 5, bCol = (tid & 31) << 2;
    int ty = tid >> 4, tx = tid & 15;
    int HW = H * W;

    int ny[4], nx[4];
    size_t nbOff[4];
#pragma unroll
    for (int j = 0; j < 4; j++) {
        int n = nBase + bCol + j;
        int b = n / HW;
        int hw = n - b * HW;
        ny[j] = hw / W; nx[j] = hw - ny[j] * W;
        nbOff[j] = (size_t)b * C * HW;
    }

    float acc[TM][8] = {};
    for (int k0 = 0; k0 < K; k0 += 8) {
        constexpr int LA = BM * 8 / 256;
#pragma unroll
        for (int i = 0; i < LA; i++) {
            int e = tid + i * 256;
            int r = e >> 3, cc = e & 7;
            int gm = mBase + r;
            As[cc][r] = (gm < M) ? A[(size_t)gm * K + k0 + cc] : 0.f;
        }
        int kr = k0 + bRow;
        int c = kr / 9;
        int t = kr - c * 9;
        int dy = t / 3 - 1;
        int dx = t - (t / 3) * 3 - 1;
        size_t cOff = (size_t)c * HW;
#pragma unroll
        for (int j = 0; j < 4; j++) {
            int iy = ny[j] + dy, ix = nx[j] + dx;
            float v = 0.f;
            if ((unsigned)iy < (unsigned)H && (unsigned)ix < (unsigned)W)
                v = X[nbOff[j] + cOff + iy * W + ix];
            Bs[bRow][bCol + j] = v;
        }
        __syncthreads();
        GEMM_INNER();
        __syncthreads();
    }
    int bI[8], hwI[8];
#pragma unroll
    for (int j = 0; j < 8; j++) {
        int n = nBase + tx * 8 + j;
        bI[j] = n / HW; hwI[j] = n - bI[j] * HW;
    }
#pragma unroll
    for (int i = 0; i < TM; i++) {
        int m = mBase + ty * TM + i;
        if (m >= M) continue;
        float bvl = bias[m];
#pragma unroll
        for (int j = 0; j < 8; j++)
            Out[((size_t)(bI[j] * M + m)) * HW + hwI[j]] = acc[i][j] + bvl;
    }
}

// ---- parity transposed-conv SGEMM; out pixel (2y+ry, 2x+rx) ----
template<int BM, int TM>
__global__ __launch_bounds__(256) void sgemm_tconv(
        const float* __restrict__ A, const float* __restrict__ X,
        const float* __restrict__ bias, float* __restrict__ Out,
        int O, int C, int K, int N, int H, int W, int ry, int rx, int lnt) {
    __shared__ float As[8][BM];
    __shared__ float Bs[8][128];
    int tid = threadIdx.x;
    int mBase = blockIdx.y * BM;
    int nBase = blockIdx.x * 128;
    int bRow = tid >> 5, bCol = (tid & 31) << 2;
    int ty = tid >> 4, tx = tid & 15;
    int HW = H * W;
    int ntm1 = (1 << lnt) - 1;

    int ny[4], nx[4];
    size_t nbOff[4];
#pragma unroll
    for (int j = 0; j < 4; j++) {
        int n = nBase + bCol + j;
        int b = n / HW;
        int hw = n - b * HW;
        ny[j] = hw / W; nx[j] = hw - ny[j] * W;
        nbOff[j] = (size_t)b * C * HW;
    }

    float acc[TM][8] = {};
    for (int k0 = 0; k0 < K; k0 += 8) {
        constexpr int LA = BM * 8 / 256;
#pragma unroll
        for (int i = 0; i < LA; i++) {
            int e = tid + i * 256;
            int r = e >> 3, cc = e & 7;
            int gm = mBase + r;
            As[cc][r] = (gm < O) ? A[(size_t)gm * K + k0 + cc] : 0.f;
        }
        int kr = k0 + bRow;
        int c = kr >> lnt;
        int t = kr & ntm1;
        int tyi = t >> rx;
        int txi = t & rx;
        int dy = ry * (1 - tyi);
        int dx = rx * (1 - txi);
        size_t cOff = (size_t)c * HW;
#pragma unroll
        for (int j = 0; j < 4; j++) {
            int iy = ny[j] + dy, ix = nx[j] + dx;
            float v = 0.f;
            if (iy < H && ix < W)
                v = X[nbOff[j] + cOff + iy * W + ix];
            Bs[bRow][bCol + j] = v;
        }
        __syncthreads();
        GEMM_INNER();
        __syncthreads();
    }
    int bI[8], yI[8], xI[8];
#pragma unroll
    for (int j = 0; j < 8; j++) {
        int n = nBase + tx * 8 + j;
        int b = n / HW;
        int hw = n - b * HW;
        bI[j] = b; yI[j] = hw / W; xI[j] = hw - yI[j] * W;
    }
    int OH = 2 * H, OW = 2 * W;
#pragma unroll
    for (int i = 0; i < TM; i++) {
        int m = mBase + ty * TM + i;
        if (m >= O) continue;
        float bvl = bias[m];
#pragma unroll
        for (int j = 0; j < 8; j++) {
            int oy = 2 * yI[j] + ry;
            int ox = 2 * xI[j] + rx;
            Out[((size_t)(bI[j] * O + m) * OH + oy) * OW + ox] = acc[i][j] + bvl;
        }
    }
}

// ---------------------------------------------------------------------------
static inline float* symaddr(const void* sym) {
    void* p = nullptr;
    cudaGetSymbolAddress(&p, sym);
    return (float*)p;
}

extern "C" void kernel_launch(void* const* d_in, const int* in_sizes, int n_in,
                              void* d_out, int out_size) {
    float* col  = symaddr(g_col);
    float* bufA = symaddr(g_bufA);
    float* bufB = symaddr(g_bufB);
    float* omb  = symaddr(g_offmod);
    float* wom  = symaddr(g_wom);
    float* bom  = symaddr(g_bom);
    float* wtp  = symaddr(g_wtp);

    struct Stage {
        const float *w_off, *b_off, *w_mod, *b_mod, *w, *b, *wt, *bt;
        int C, H, W, O;
    };
    Stage st[3];
    for (int i = 0; i < 3; i++) {
        int base = 1 + i * 8;
        st[i].w_off = (const float*)d_in[base + 0];
        st[i].b_off = (const float*)d_in[base + 1];
        st[i].w_mod = (const float*)d_in[base + 2];
        st[i].b_mod = (const float*)d_in[base + 3];
        st[i].w     = (const float*)d_in[base + 4];
        st[i].b     = (const float*)d_in[base + 5];
        st[i].wt    = (const float*)d_in[base + 6];
        st[i].bt    = (const float*)d_in[base + 7];
    }
    st[0].C = 512; st[0].H = 32;  st[0].W = 32;  st[0].O = 256;
    st[1].C = 256; st[1].H = 64;  st[1].W = 64;  st[1].O = 128;
    st[2].C = 128; st[2].H = 128; st[2].W = 128; st[2].O = 64;

    const float* X = (const float*)d_in[0];

    for (int i = 0; i < 3; i++) {
        int C = st[i].C, H = st[i].H, W = st[i].W, O = st[i].O;
        int HW = H * W;
        int N = BATCH * HW;
        int K9 = C * 9;

        build_wom<<<(27 * K9 + 255) / 256, 256>>>(st[i].w_off, st[i].b_off,
                                                  st[i].w_mod, st[i].b_mod,
                                                  wom, bom, K9);
        sgemm_c3x3<32, 2><<<dim3(N / 128, 1), 256>>>(wom, X, bom, omb,
                                                     27, C, K9, N, H, W);
        deform_im2col<<<(9 * N + 255) / 256, 256>>>(X, omb, col, C, H, W, N);

        float* Y = bufA;
        if (O >= 128)
            sgemm_col<128, 8><<<dim3(N / 128, (O + 127) / 128), 256>>>(
                st[i].w, col, st[i].b, Y, O, K9, N, HW);
        else
            sgemm_col<64, 4><<<dim3(N / 128, 1), 256>>>(
                st[i].w, col, st[i].b, Y, O, K9, N, HW);

        float* Xn = (i == 2) ? (float*)d_out : bufB;
        int OO = O * O;
        int offp[4] = {0, OO, 3 * OO, 5 * OO};
        int ntp[4]  = {1, 2, 2, 4};
        int lntp[4] = {0, 1, 1, 2};
        for (int p = 0; p < 4; p++) {
            int ry = p >> 1, rx = p & 1;
            build_wtp<<<(OO * ntp[p] + 255) / 256, 256>>>(st[i].wt, wtp + offp[p],
                                                          O, ntp[p], ry, rx);
            int Kp = O * ntp[p];
            if (O >= 128)
                sgemm_tconv<128, 8><<<dim3(N / 128, (O + 127) / 128), 256>>>(
                    wtp + offp[p], Y, st[i].bt, Xn, O, O, Kp, N, H, W, ry, rx, lntp[p]);
            else
                sgemm_tconv<64, 4><<<dim3(N / 128, 1), 256>>>(
                    wtp + offp[p], Y, st[i].bt, Xn, O, O, Kp, N, H, W, ry, rx, lntp[p]);
        }
        X = Xn;
    }
}

// round 4
// speedup vs baseline: 2.2553x; 1.1529x over previous
#include <cuda_runtime.h>
#include <cstdint>

// ---------------------------------------------------------------------------
// Neck: 3 x (modulated deformable 3x3 conv -> ConvTranspose2d(k3,s2,p1,op1))
//  - off/mod convs: fused-im2col GEMM (M=27 padded to 32)
//  - deform conv:   deform_im2col -> SGEMM
//  - tconv:         parity-decomposed, im2col fused into GEMM
//  All GEMMs: pre-transposed A + double-buffered smem pipeline.
// ---------------------------------------------------------------------------

#define BATCH 8

__device__ float g_col[150994944];   // deform col: max K=4608 x N=8192 (=stage1) etc.
__device__ float g_bufA[8388608];    // deform outputs Y
__device__ float g_bufB[16777216];   // tconv outputs
__device__ float g_offmod[3538944];  // [B,27,HW] off+mod conv out
__device__ float g_womT[147456];     // [K, 32] transposed padded off/mod weights
__device__ float g_bom[32];
__device__ float g_wT[1179648];      // [K9, O] transposed deform weights
__device__ float g_wtpT[589824];     // transposed parity tconv weights, 9*O*O total

// ---------------------------------------------------------------------------
// Weight prep kernels
// ---------------------------------------------------------------------------
__global__ void transpose_w(const float* __restrict__ src, float* __restrict__ dst,
                            int M, int K) {
    int idx = blockIdx.x * blockDim.x + threadIdx.x;
    if (idx >= M * K) return;
    int m = idx / K;
    int k = idx - m * K;
    dst[(size_t)k * M + m] = src[idx];
}

__global__ void build_womT(const float* __restrict__ w_off, const float* __restrict__ b_off,
                           const float* __restrict__ w_mod, const float* __restrict__ b_mod,
                           float* __restrict__ womT, float* __restrict__ bom, int K) {
    int idx = blockIdx.x * blockDim.x + threadIdx.x;
    if (idx < 32) bom[idx] = (idx < 18) ? b_off[idx] : (idx < 27 ? b_mod[idx - 18] : 0.f);
    if (idx >= 32 * K) return;
    int k = idx >> 5;
    int m = idx & 31;
    float v = 0.f;
    if (m < 18)      v = w_off[(size_t)m * K + k];
    else if (m < 27) v = w_mod[(size_t)(m - 18) * K + k];
    womT[idx] = v;
}

// All 4 parity regions in one launch. Region p at float offset {0,1,3,5}*O*O,
// layout [Kp][O] with Kp = O*nt, k = c*nt + t.
__global__ void build_wtpT(const float* __restrict__ wt, float* __restrict__ out, int O) {
    int idx = blockIdx.x * blockDim.x + threadIdx.x;
    int OO = O * O;
    if (idx >= 9 * OO) return;
    int p, base, nt;
    if (idx < OO)          { p = 0; base = 0;      nt = 1; }
    else if (idx < 3 * OO) { p = 1; base = OO;     nt = 2; }
    else if (idx < 5 * OO) { p = 2; base = 3 * OO; nt = 2; }
    else                   { p = 3; base = 5 * OO; nt = 4; }
    int r = idx - base;
    int o = r % O;
    int k = r / O;
    int c = k / nt;
    int t = k - c * nt;
    int ry = p >> 1, rx = p & 1;
    int ntx = rx + 1;
    int tyi = t / ntx;
    int txi = t - tyi * ntx;
    int ky = ry ? (tyi ? 2 : 0) : 1;
    int kx = rx ? (txi ? 2 : 0) : 1;
    out[idx] = wt[((size_t)(c * O + o)) * 9 + ky * 3 + kx];
}

// ---------------------------------------------------------------------------
__global__ void deform_im2col(const float* __restrict__ x,
                              const float* __restrict__ om,
                              float* __restrict__ col,
                              int C, int H, int W, int N) {
    int idx = blockIdx.x * blockDim.x + threadIdx.x;
    if (idx >= 9 * N) return;
    int n = idx % N;
    int k = idx / N;
    int HW = H * W;
    int hw = n % HW;
    int b  = n / HW;
    int h = hw / W, w = hw % W;

    float dy = om[((size_t)(b * 27 + 2 * k)) * HW + hw];
    float dx = om[((size_t)(b * 27 + 2 * k + 1)) * HW + hw];
    float mr = om[((size_t)(b * 27 + 18 + k)) * HW + hw];
    float m  = 1.f / (1.f + expf(-mr));

    float py = dy + (float)(k / 3 - 1) + (float)h;
    float px = dx + (float)(k % 3 - 1) + (float)w;

    float y0f = floorf(py), x0f = floorf(px);
    float wy = py - y0f, wx = px - x0f;
    int y0 = (int)y0f, x0 = (int)x0f;
    int y1 = y0 + 1,   x1 = x0 + 1;

    bool vy0 = (y0 >= 0) && (y0 <= H - 1);
    bool vy1 = (y1 >= 0) && (y1 <= H - 1);
    bool vx0 = (x0 >= 0) && (x0 <= W - 1);
    bool vx1 = (x1 >= 0) && (x1 <= W - 1);

    int y0c = min(max(y0, 0), H - 1);
    int y1c = min(max(y1, 0), H - 1);
    int x0c = min(max(x0, 0), W - 1);
    int x1c = min(max(x1, 0), W - 1);

    float w00 = (1.f - wy) * (1.f - wx) * ((vy0 && vx0) ? m : 0.f);
    float w01 = (1.f - wy) * wx         * ((vy0 && vx1) ? m : 0.f);
    float w10 = wy * (1.f - wx)         * ((vy1 && vx0) ? m : 0.f);
    float w11 = wy * wx                 * ((vy1 && vx1) ? m : 0.f);

    int i00 = y0c * W + x0c;
    int i01 = y0c * W + x1c;
    int i10 = y1c * W + x0c;
    int i11 = y1c * W + x1c;

    const float* xb = x + (size_t)b * C * HW;
    size_t ob = (size_t)k * N + n;
    size_t stride = (size_t)9 * N;
    for (int c = 0; c < C; c++) {
        const float* xc = xb + (size_t)c * HW;
        float v = w00 * xc[i00] + w01 * xc[i01] + w10 * xc[i10] + w11 * xc[i11];
        col[ob + (size_t)c * stride] = v;
    }
}

// ---------------------------------------------------------------------------
// GEMM building blocks. A pre-transposed: At[K][lda], tile load = 1 float4.
// Double buffered smem, BK=8, BN=128, 256 threads, TN=8.
// ---------------------------------------------------------------------------
#define GEMM_COMPUTE(BUF)                                                 \
    _Pragma("unroll")                                                     \
    for (int kk = 0; kk < 8; kk++) {                                      \
        float ar[TM], br[8];                                              \
        _Pragma("unroll")                                                 \
        for (int i = 0; i < TM; i++) ar[i] = As[BUF][kk][ty * TM + i];    \
        _Pragma("unroll")                                                 \
        for (int j = 0; j < 8; j++) br[j] = Bs[BUF][kk][tx * 8 + j];      \
        _Pragma("unroll")                                                 \
        for (int i = 0; i < TM; i++)                                      \
            _Pragma("unroll")                                             \
            for (int j = 0; j < 8; j++) acc[i][j] += ar[i] * br[j];       \
    }

// ---- col-based SGEMM (deform conv): requires M % BM == 0, N % 128 == 0 ----
template<int BM, int TM>
__global__ __launch_bounds__(256) void sgemm_col(
        const float* __restrict__ At, const float* __restrict__ B,
        const float* __restrict__ bias, float* __restrict__ Out,
        int M, int K, int N, int HW) {
    __shared__ float As[2][8][BM];
    __shared__ float Bs[2][8][128];
    const int tid = threadIdx.x;
    const int mBase = blockIdx.y * BM;
    const int nBase = blockIdx.x * 128;
    constexpr int TPR = BM / 4;
    const int aRow = tid / TPR;
    const int aCol = (tid % TPR) * 4;
    const bool aAct = (tid < 8 * TPR);
    const int bRow = tid >> 5, bCol = (tid & 31) << 2;
    const int ty = tid >> 4, tx = tid & 15;

    float acc[TM][8] = {};
    float4 aReg, bReg;

    // preload tile 0
    aReg = aAct ? *reinterpret_cast<const float4*>(&At[(size_t)aRow * M + mBase + aCol])
                : make_float4(0.f, 0.f, 0.f, 0.f);
    bReg = *reinterpret_cast<const float4*>(&B[(size_t)bRow * N + nBase + bCol]);
    if (aAct) *reinterpret_cast<float4*>(&As[0][aRow][aCol]) = aReg;
    *reinterpret_cast<float4*>(&Bs[0][bRow][bCol]) = bReg;
    __syncthreads();

    int buf = 0;
    for (int k0 = 8; k0 < K; k0 += 8) {
        aReg = aAct ? *reinterpret_cast<const float4*>(&At[(size_t)(k0 + aRow) * M + mBase + aCol])
                    : make_float4(0.f, 0.f, 0.f, 0.f);
        bReg = *reinterpret_cast<const float4*>(&B[(size_t)(k0 + bRow) * N + nBase + bCol]);
        GEMM_COMPUTE(buf);
        if (aAct) *reinterpret_cast<float4*>(&As[buf ^ 1][aRow][aCol]) = aReg;
        *reinterpret_cast<float4*>(&Bs[buf ^ 1][bRow][bCol]) = bReg;
        buf ^= 1;
        __syncthreads();
    }
    GEMM_COMPUTE(buf);

    int bI[8], hwI[8];
#pragma unroll
    for (int j = 0; j < 8; j++) {
        int n = nBase + tx * 8 + j;
        bI[j] = n / HW; hwI[j] = n - bI[j] * HW;
    }
#pragma unroll
    for (int i = 0; i < TM; i++) {
        int m = mBase + ty * TM + i;
        float bvl = bias[m];
#pragma unroll
        for (int j = 0; j < 8; j++)
            Out[((size_t)(bI[j] * M + m)) * HW + hwI[j]] = acc[i][j] + bvl;
    }
}

// ---- fused 3x3-conv SGEMM (off/mod, M=27 padded to lda=32=BM) ----
template<int BM, int TM>
__global__ __launch_bounds__(256) void sgemm_c3x3(
        const float* __restrict__ At, const float* __restrict__ X,
        const float* __restrict__ bias, float* __restrict__ Out,
        int M, int C, int K, int N, int H, int W) {
    __shared__ float As[2][8][BM];
    __shared__ float Bs[2][8][128];
    const int tid = threadIdx.x;
    const int nBase = blockIdx.x * 128;
    constexpr int TPR = BM / 4;
    const int aRow = tid / TPR;
    const int aCol = (tid % TPR) * 4;
    const bool aAct = (tid < 8 * TPR);
    const int bRow = tid >> 5, bCol = (tid & 31) << 2;
    const int ty = tid >> 4, tx = tid & 15;
    const int HW = H * W;

    int ny[4], nx[4];
    size_t nbOff[4];
#pragma unroll
    for (int j = 0; j < 4; j++) {
        int n = nBase + bCol + j;
        int b = n / HW;
        int hw = n - b * HW;
        ny[j] = hw / W; nx[j] = hw - ny[j] * W;
        nbOff[j] = (size_t)b * C * HW;
    }

    float acc[TM][8] = {};
    float4 aReg;
    float bv[4];

    // B gather for tile at k0
#define C3X3_GATHER(K0)                                                       \
    {                                                                         \
        int kr = (K0) + bRow;                                                 \
        int c = kr / 9;                                                       \
        int t = kr - c * 9;                                                   \
        int q = t / 3;                                                        \
        int dy = q - 1, dx = t - q * 3 - 1;                                   \
        size_t cOff = (size_t)c * HW;                                         \
        _Pragma("unroll")                                                     \
        for (int j = 0; j < 4; j++) {                                         \
            int iy = ny[j] + dy, ix = nx[j] + dx;                             \
            bv[j] = ((unsigned)iy < (unsigned)H && (unsigned)ix < (unsigned)W) \
                        ? X[nbOff[j] + cOff + iy * W + ix] : 0.f;             \
        }                                                                     \
    }

    aReg = aAct ? *reinterpret_cast<const float4*>(&At[(size_t)aRow * BM + aCol])
                : make_float4(0.f, 0.f, 0.f, 0.f);
    C3X3_GATHER(0);
    if (aAct) *reinterpret_cast<float4*>(&As[0][aRow][aCol]) = aReg;
#pragma unroll
    for (int j = 0; j < 4; j++) Bs[0][bRow][bCol + j] = bv[j];
    __syncthreads();

    int buf = 0;
    for (int k0 = 8; k0 < K; k0 += 8) {
        aReg = aAct ? *reinterpret_cast<const float4*>(&At[(size_t)(k0 + aRow) * BM + aCol])
                    : make_float4(0.f, 0.f, 0.f, 0.f);
        C3X3_GATHER(k0);
        GEMM_COMPUTE(buf);
        if (aAct) *reinterpret_cast<float4*>(&As[buf ^ 1][aRow][aCol]) = aReg;
#pragma unroll
        for (int j = 0; j < 4; j++) Bs[buf ^ 1][bRow][bCol + j] = bv[j];
        buf ^= 1;
        __syncthreads();
    }
    GEMM_COMPUTE(buf);
#undef C3X3_GATHER

    int bI[8], hwI[8];
#pragma unroll
    for (int j = 0; j < 8; j++) {
        int n = nBase + tx * 8 + j;
        bI[j] = n / HW; hwI[j] = n - bI[j] * HW;
    }
#pragma unroll
    for (int i = 0; i < TM; i++) {
        int m = ty * TM + i;
        if (m >= M) continue;
        float bvl = bias[m];
#pragma unroll
        for (int j = 0; j < 8; j++)
            Out[((size_t)(bI[j] * M + m)) * HW + hwI[j]] = acc[i][j] + bvl;
    }
}

// ---- parity transposed-conv SGEMM; out pixel (2y+ry, 2x+rx); O % BM == 0 ----
template<int BM, int TM>
__global__ __launch_bounds__(256) void sgemm_tconv(
        const float* __restrict__ At, const float* __restrict__ X,
        const float* __restrict__ bias, float* __restrict__ Out,
        int O, int K, int N, int H, int W, int ry, int rx, int lnt) {
    __shared__ float As[2][8][BM];
    __shared__ float Bs[2][8][128];
    const int tid = threadIdx.x;
    const int mBase = blockIdx.y * BM;
    const int nBase = blockIdx.x * 128;
    constexpr int TPR = BM / 4;
    const int aRow = tid / TPR;
    const int aCol = (tid % TPR) * 4;
    const bool aAct = (tid < 8 * TPR);
    const int bRow = tid >> 5, bCol = (tid & 31) << 2;
    const int ty = tid >> 4, tx = tid & 15;
    const int HW = H * W;
    const int ntm1 = (1 << lnt) - 1;

    int ny[4], nx[4];
    size_t nbOff[4];
#pragma unroll
    for (int j = 0; j < 4; j++) {
        int n = nBase + bCol + j;
        int b = n / HW;
        int hw = n - b * HW;
        ny[j] = hw / W; nx[j] = hw - ny[j] * W;
        nbOff[j] = (size_t)b * O * HW;
    }

    float acc[TM][8] = {};
    float4 aReg;
    float bv[4];

#define TC_GATHER(K0)                                                 \
    {                                                                 \
        int kr = (K0) + bRow;                                         \
        int c = kr >> lnt;                                            \
        int t = kr & ntm1;                                            \
        int tyi = t >> rx;                                            \
        int txi = t & rx;                                             \
        int dy = ry * (1 - tyi);                                      \
        int dx = rx * (1 - txi);                                      \
        size_t cOff = (size_t)c * HW;                                 \
        _Pragma("unroll")                                             \
        for (int j = 0; j < 4; j++) {                                 \
            int iy = ny[j] + dy, ix = nx[j] + dx;                     \
            bv[j] = (iy < H && ix < W)                                \
                        ? X[nbOff[j] + cOff + iy * W + ix] : 0.f;     \
        }                                                             \
    }

    aReg = aAct ? *reinterpret_cast<const float4*>(&At[(size_t)aRow * O + mBase + aCol])
                : make_float4(0.f, 0.f, 0.f, 0.f);
    TC_GATHER(0);
    if (aAct) *reinterpret_cast<float4*>(&As[0][aRow][aCol]) = aReg;
#pragma unroll
    for (int j = 0; j < 4; j++) Bs[0][bRow][bCol + j] = bv[j];
    __syncthreads();

    int buf = 0;
    for (int k0 = 8; k0 < K; k0 += 8) {
        aReg = aAct ? *reinterpret_cast<const float4*>(&At[(size_t)(k0 + aRow) * O + mBase + aCol])
                    : make_float4(0.f, 0.f, 0.f, 0.f);
        TC_GATHER(k0);
        GEMM_COMPUTE(buf);
        if (aAct) *reinterpret_cast<float4*>(&As[buf ^ 1][aRow][aCol]) = aReg;
#pragma unroll
        for (int j = 0; j < 4; j++) Bs[buf ^ 1][bRow][bCol + j] = bv[j];
        buf ^= 1;
        __syncthreads();
    }
    GEMM_COMPUTE(buf);
#undef TC_GATHER

    int bI[8], yI[8], xI[8];
#pragma unroll
    for (int j = 0; j < 8; j++) {
        int n = nBase + tx * 8 + j;
        int b = n / HW;
        int hw = n - b * HW;
        bI[j] = b; yI[j] = hw / W; xI[j] = hw - yI[j] * W;
    }
    int OH = 2 * H, OW = 2 * W;
#pragma unroll
    for (int i = 0; i < TM; i++) {
        int m = mBase + ty * TM + i;
        float bvl = bias[m];
#pragma unroll
        for (int j = 0; j < 8; j++) {
            int oy = 2 * yI[j] + ry;
            int ox = 2 * xI[j] + rx;
            Out[((size_t)(bI[j] * O + m) * OH + oy) * OW + ox] = acc[i][j] + bvl;
        }
    }
}

// ---------------------------------------------------------------------------
static inline float* symaddr(const void* sym) {
    void* p = nullptr;
    cudaGetSymbolAddress(&p, sym);
    return (float*)p;
}

extern "C" void kernel_launch(void* const* d_in, const int* in_sizes, int n_in,
                              void* d_out, int out_size) {
    float* col   = symaddr(g_col);
    float* bufA  = symaddr(g_bufA);
    float* bufB  = symaddr(g_bufB);
    float* omb   = symaddr(g_offmod);
    float* womT  = symaddr(g_womT);
    float* bom   = symaddr(g_bom);
    float* wT    = symaddr(g_wT);
    float* wtpT  = symaddr(g_wtpT);

    struct Stage {
        const float *w_off, *b_off, *w_mod, *b_mod, *w, *b, *wt, *bt;
        int C, H, W, O;
    };
    Stage st[3];
    for (int i = 0; i < 3; i++) {
        int base = 1 + i * 8;
        st[i].w_off = (const float*)d_in[base + 0];
        st[i].b_off = (const float*)d_in[base + 1];
        st[i].w_mod = (const float*)d_in[base + 2];
        st[i].b_mod = (const float*)d_in[base + 3];
        st[i].w     = (const float*)d_in[base + 4];
        st[i].b     = (const float*)d_in[base + 5];
        st[i].wt    = (const float*)d_in[base + 6];
        st[i].bt    = (const float*)d_in[base + 7];
    }
    st[0].C = 512; st[0].H = 32;  st[0].W = 32;  st[0].O = 256;
    st[1].C = 256; st[1].H = 64;  st[1].W = 64;  st[1].O = 128;
    st[2].C = 128; st[2].H = 128; st[2].W = 128; st[2].O = 64;

    const float* X = (const float*)d_in[0];

    for (int i = 0; i < 3; i++) {
        int C = st[i].C, H = st[i].H, W = st[i].W, O = st[i].O;
        int HW = H * W;
        int N = BATCH * HW;
        int K9 = C * 9;

        // weight prep
        build_womT<<<(32 * K9 + 255) / 256, 256>>>(st[i].w_off, st[i].b_off,
                                                   st[i].w_mod, st[i].b_mod,
                                                   womT, bom, K9);
        transpose_w<<<(O * K9 + 255) / 256, 256>>>(st[i].w, wT, O, K9);
        build_wtpT<<<(9 * O * O + 255) / 256, 256>>>(st[i].wt, wtpT, O);

        // off/mod conv (fused im2col GEMM, M=27, lda=BM=32)
        sgemm_c3x3<32, 2><<<dim3(N / 128, 1), 256>>>(womT, X, bom, omb,
                                                     27, C, K9, N, H, W);
        // deformable im2col
        deform_im2col<<<(9 * N + 255) / 256, 256>>>(X, omb, col, C, H, W, N);

        // main deform conv GEMM
        float* Y = bufA;
        if (O >= 128)
            sgemm_col<128, 8><<<dim3(N / 128, O / 128), 256>>>(
                wT, col, st[i].b, Y, O, K9, N, HW);
        else
            sgemm_col<64, 4><<<dim3(N / 128, 1), 256>>>(
                wT, col, st[i].b, Y, O, K9, N, HW);

        // parity-decomposed transposed conv
        float* Xn = (i == 2) ? (float*)d_out : bufB;
        int OO = O * O;
        int offp[4] = {0, OO, 3 * OO, 5 * OO};
        int ntp[4]  = {1, 2, 2, 4};
        int lntp[4] = {0, 1, 1, 2};
        for (int p = 0; p < 4; p++) {
            int ry = p >> 1, rx = p & 1;
            int Kp = O * ntp[p];
            if (O >= 128)
                sgemm_tconv<128, 8><<<dim3(N / 128, O / 128), 256>>>(
                    wtpT + offp[p], Y, st[i].bt, Xn, O, Kp, N, H, W, ry, rx, lntp[p]);
            else
                sgemm_tconv<64, 4><<<dim3(N / 128, 1), 256>>>(
                    wtpT + offp[p], Y, st[i].bt, Xn, O, Kp, N, H, W, ry, rx, lntp[p]);
        }
        X = Xn;
    }
}

// round 5
// speedup vs baseline: 2.4785x; 1.0990x over previous
#include <cuda_runtime.h>
#include <cstdint>

// ---------------------------------------------------------------------------
// Neck: 3 x (modulated deformable 3x3 conv -> ConvTranspose2d(k3,s2,p1,op1))
//  - off/mod convs: fused-im2col GEMM (M=27 pad 32), split-K when N small
//  - deform conv:   deform_im2col -> SGEMM, split-K when N small
//  - tconv:         parity-decomposed, all 4 parities batched in one launch
//  All GEMMs: pre-transposed A + double-buffered smem pipeline.
// ---------------------------------------------------------------------------

#define BATCH 8

__device__ float g_col[150994944];   // deform col: K x N (max stage: 1152x131072)
__device__ float g_bufA[8388608];    // deform outputs Y
__device__ float g_bufB[16777216];   // tconv outputs
__device__ float g_offmod[3538944];  // [B,27,HW] off+mod conv out
__device__ float g_part[8388608];    // split-K partials (max 4*256*8192)
__device__ float g_womT[147456];     // [K,32] transposed padded off/mod weights
__device__ float g_bom[32];
__device__ float g_wT[1179648];      // [K9,O] transposed deform weights
__device__ float g_wtpT[589824];     // transposed parity tconv weights

// ---------------------------------------------------------------------------
// Weight prep
// ---------------------------------------------------------------------------
__global__ void transpose_w(const float* __restrict__ src, float* __restrict__ dst,
                            int M, int K) {
    int idx = blockIdx.x * blockDim.x + threadIdx.x;
    if (idx >= M * K) return;
    int m = idx / K;
    int k = idx - m * K;
    dst[(size_t)k * M + m] = src[idx];
}

__global__ void build_womT(const float* __restrict__ w_off, const float* __restrict__ b_off,
                           const float* __restrict__ w_mod, const float* __restrict__ b_mod,
                           float* __restrict__ womT, float* __restrict__ bom, int K) {
    int idx = blockIdx.x * blockDim.x + threadIdx.x;
    if (idx < 32) bom[idx] = (idx < 18) ? b_off[idx] : (idx < 27 ? b_mod[idx - 18] : 0.f);
    if (idx >= 32 * K) return;
    int k = idx >> 5;
    int m = idx & 31;
    float v = 0.f;
    if (m < 18)      v = w_off[(size_t)m * K + k];
    else if (m < 27) v = w_mod[(size_t)(m - 18) * K + k];
    womT[idx] = v;
}

// parity regions at float offsets {0,1,3,5}*O*O, layout [Kp][O], k=c*nt+t
__global__ void build_wtpT(const float* __restrict__ wt, float* __restrict__ out, int O) {
    int idx = blockIdx.x * blockDim.x + threadIdx.x;
    int OO = O * O;
    if (idx >= 9 * OO) return;
    int p, base, nt;
    if (idx < OO)          { p = 0; base = 0;      nt = 1; }
    else if (idx < 3 * OO) { p = 1; base = OO;     nt = 2; }
    else if (idx < 5 * OO) { p = 2; base = 3 * OO; nt = 2; }
    else                   { p = 3; base = 5 * OO; nt = 4; }
    int r = idx - base;
    int o = r % O;
    int k = r / O;
    int c = k / nt;
    int t = k - c * nt;
    int ry = p >> 1, rx = p & 1;
    int ntx = rx + 1;
    int tyi = t / ntx;
    int txi = t - tyi * ntx;
    int ky = ry ? (tyi ? 2 : 0) : 1;
    int kx = rx ? (txi ? 2 : 0) : 1;
    out[idx] = wt[((size_t)(c * O + o)) * 9 + ky * 3 + kx];
}

// ---------------------------------------------------------------------------
__global__ void deform_im2col(const float* __restrict__ x,
                              const float* __restrict__ om,
                              float* __restrict__ col,
                              int C, int H, int W, int N) {
    int idx = blockIdx.x * blockDim.x + threadIdx.x;
    if (idx >= 9 * N) return;
    int n = idx % N;
    int k = idx / N;
    int HW = H * W;
    int hw = n % HW;
    int b  = n / HW;
    int h = hw / W, w = hw % W;

    float dy = om[((size_t)(b * 27 + 2 * k)) * HW + hw];
    float dx = om[((size_t)(b * 27 + 2 * k + 1)) * HW + hw];
    float mr = om[((size_t)(b * 27 + 18 + k)) * HW + hw];
    float m  = 1.f / (1.f + expf(-mr));

    float py = dy + (float)(k / 3 - 1) + (float)h;
    float px = dx + (float)(k % 3 - 1) + (float)w;

    float y0f = floorf(py), x0f = floorf(px);
    float wy = py - y0f, wx = px - x0f;
    int y0 = (int)y0f, x0 = (int)x0f;
    int y1 = y0 + 1,   x1 = x0 + 1;

    bool vy0 = (y0 >= 0) && (y0 <= H - 1);
    bool vy1 = (y1 >= 0) && (y1 <= H - 1);
    bool vx0 = (x0 >= 0) && (x0 <= W - 1);
    bool vx1 = (x1 >= 0) && (x1 <= W - 1);

    int y0c = min(max(y0, 0), H - 1);
    int y1c = min(max(y1, 0), H - 1);
    int x0c = min(max(x0, 0), W - 1);
    int x1c = min(max(x1, 0), W - 1);

    float w00 = (1.f - wy) * (1.f - wx) * ((vy0 && vx0) ? m : 0.f);
    float w01 = (1.f - wy) * wx         * ((vy0 && vx1) ? m : 0.f);
    float w10 = wy * (1.f - wx)         * ((vy1 && vx0) ? m : 0.f);
    float w11 = wy * wx                 * ((vy1 && vx1) ? m : 0.f);

    int i00 = y0c * W + x0c;
    int i01 = y0c * W + x1c;
    int i10 = y1c * W + x0c;
    int i11 = y1c * W + x1c;

    const float* xb = x + (size_t)b * C * HW;
    size_t ob = (size_t)k * N + n;
    size_t stride = (size_t)9 * N;
    for (int c = 0; c < C; c++) {
        const float* xc = xb + (size_t)c * HW;
        float v = w00 * xc[i00] + w01 * xc[i01] + w10 * xc[i10] + w11 * xc[i11];
        col[ob + (size_t)c * stride] = v;
    }
}

// ---------------------------------------------------------------------------
// split-K reduce: out NCHW = sum_s part[s][m][n] + bias[m]
// ---------------------------------------------------------------------------
__global__ void reduce_part(const float* __restrict__ part, const float* __restrict__ bias,
                            float* __restrict__ out, int M, int Mpad, int N, int HW, int S) {
    int idx = blockIdx.x * blockDim.x + threadIdx.x;
    int nv = N >> 2;
    if (idx >= M * nv) return;
    int m = idx / nv;
    int n4 = (idx - m * nv) << 2;
    size_t off = (size_t)m * N + n4;
    float4 s = *reinterpret_cast<const float4*>(&part[off]);
    size_t sl = (size_t)Mpad * N;
    for (int si = 1; si < S; si++) {
        float4 p = *reinterpret_cast<const float4*>(&part[(size_t)si * sl + off]);
        s.x += p.x; s.y += p.y; s.z += p.z; s.w += p.w;
    }
    float bv = bias[m];
    s.x += bv; s.y += bv; s.z += bv; s.w += bv;
    int b = n4 / HW;
    int hw = n4 - b * HW;
    *reinterpret_cast<float4*>(&out[((size_t)(b * M + m)) * HW + hw]) = s;
}

// ---------------------------------------------------------------------------
// GEMM core. A pre-transposed At[K][lda]. Double buffered, BK=8, BN=128,
// 256 threads, TN=8.
// ---------------------------------------------------------------------------
#define GEMM_COMPUTE(BUF)                                                 \
    _Pragma("unroll")                                                     \
    for (int kk = 0; kk < 8; kk++) {                                      \
        float ar[TM], br[8];                                              \
        _Pragma("unroll")                                                 \
        for (int i = 0; i < TM; i++) ar[i] = As[BUF][kk][ty * TM + i];    \
        _Pragma("unroll")                                                 \
        for (int j = 0; j < 8; j++) br[j] = Bs[BUF][kk][tx * 8 + j];      \
        _Pragma("unroll")                                                 \
        for (int i = 0; i < TM; i++)                                      \
            _Pragma("unroll")                                             \
            for (int j = 0; j < 8; j++) acc[i][j] += ar[i] * br[j];       \
    }

// ---- col-based SGEMM (deform conv), optional split-K ----
// part != nullptr: write partial [z][m][n]; else NCHW + bias.
template<int BM, int TM>
__global__ __launch_bounds__(256) void sgemm_col(
        const float* __restrict__ At, const float* __restrict__ B,
        const float* __restrict__ bias, float* __restrict__ Out,
        float* __restrict__ part,
        int M, int N, int HW, int Kslice) {
    __shared__ float As[2][8][BM];
    __shared__ float Bs[2][8][128];
    const int tid = threadIdx.x;
    const int mBase = blockIdx.y * BM;
    const int nBase = blockIdx.x * 128;
    const int kBegin = blockIdx.z * Kslice;
    const int kEnd = kBegin + Kslice;
    constexpr int TPR = BM / 4;
    const int aRow = tid / TPR;
    const int aCol = (tid % TPR) * 4;
    const bool aAct = (tid < 8 * TPR);
    const int bRow = tid >> 5, bCol = (tid & 31) << 2;
    const int ty = tid >> 4, tx = tid & 15;

    float acc[TM][8] = {};
    float4 aReg, bReg;

    aReg = aAct ? *reinterpret_cast<const float4*>(&At[(size_t)(kBegin + aRow) * M + mBase + aCol])
                : make_float4(0.f, 0.f, 0.f, 0.f);
    bReg = *reinterpret_cast<const float4*>(&B[(size_t)(kBegin + bRow) * N + nBase + bCol]);
    if (aAct) *reinterpret_cast<float4*>(&As[0][aRow][aCol]) = aReg;
    *reinterpret_cast<float4*>(&Bs[0][bRow][bCol]) = bReg;
    __syncthreads();

    int buf = 0;
    for (int k0 = kBegin + 8; k0 < kEnd; k0 += 8) {
        aReg = aAct ? *reinterpret_cast<const float4*>(&At[(size_t)(k0 + aRow) * M + mBase + aCol])
                    : make_float4(0.f, 0.f, 0.f, 0.f);
        bReg = *reinterpret_cast<const float4*>(&B[(size_t)(k0 + bRow) * N + nBase + bCol]);
        GEMM_COMPUTE(buf);
        if (aAct) *reinterpret_cast<float4*>(&As[buf ^ 1][aRow][aCol]) = aReg;
        *reinterpret_cast<float4*>(&Bs[buf ^ 1][bRow][bCol]) = bReg;
        buf ^= 1;
        __syncthreads();
    }
    GEMM_COMPUTE(buf);

    if (part) {
        float* p = part + (size_t)blockIdx.z * M * N;
#pragma unroll
        for (int i = 0; i < TM; i++) {
            int m = mBase + ty * TM + i;
#pragma unroll
            for (int j = 0; j < 8; j += 4) {
                int n = nBase + tx * 8 + j;
                *reinterpret_cast<float4*>(&p[(size_t)m * N + n]) =
                    make_float4(acc[i][j], acc[i][j + 1], acc[i][j + 2], acc[i][j + 3]);
            }
        }
    } else {
        int bI[8], hwI[8];
#pragma unroll
        for (int j = 0; j < 8; j++) {
            int n = nBase + tx * 8 + j;
            bI[j] = n / HW; hwI[j] = n - bI[j] * HW;
        }
#pragma unroll
        for (int i = 0; i < TM; i++) {
            int m = mBase + ty * TM + i;
            float bvl = bias[m];
#pragma unroll
            for (int j = 0; j < 8; j++)
                Out[((size_t)(bI[j] * M + m)) * HW + hwI[j]] = acc[i][j] + bvl;
        }
    }
}

// ---- fused 3x3-conv SGEMM (off/mod, M=27 pad 32), optional split-K ----
template<int BM, int TM>
__global__ __launch_bounds__(256) void sgemm_c3x3(
        const float* __restrict__ At, const float* __restrict__ X,
        const float* __restrict__ bias, float* __restrict__ Out,
        float* __restrict__ part,
        int M, int C, int N, int H, int W, int Kslice) {
    __shared__ float As[2][8][BM];
    __shared__ float Bs[2][8][128];
    const int tid = threadIdx.x;
    const int nBase = blockIdx.x * 128;
    const int kBegin = blockIdx.z * Kslice;
    const int kEnd = kBegin + Kslice;
    constexpr int TPR = BM / 4;
    const int aRow = tid / TPR;
    const int aCol = (tid % TPR) * 4;
    const bool aAct = (tid < 8 * TPR);
    const int bRow = tid >> 5, bCol = (tid & 31) << 2;
    const int ty = tid >> 4, tx = tid & 15;
    const int HW = H * W;

    int ny[4], nx[4];
    size_t nbOff[4];
#pragma unroll
    for (int j = 0; j < 4; j++) {
        int n = nBase + bCol + j;
        int b = n / HW;
        int hw = n - b * HW;
        ny[j] = hw / W; nx[j] = hw - ny[j] * W;
        nbOff[j] = (size_t)b * C * HW;
    }

    float acc[TM][8] = {};
    float4 aReg;
    float bv[4];

#define C3X3_GATHER(K0)                                                       \
    {                                                                         \
        int kr = (K0) + bRow;                                                 \
        int c = kr / 9;                                                       \
        int t = kr - c * 9;                                                   \
        int q = t / 3;                                                        \
        int dy = q - 1, dx = t - q * 3 - 1;                                   \
        size_t cOff = (size_t)c * HW;                                         \
        _Pragma("unroll")                                                     \
        for (int j = 0; j < 4; j++) {                                         \
            int iy = ny[j] + dy, ix = nx[j] + dx;                             \
            bv[j] = ((unsigned)iy < (unsigned)H && (unsigned)ix < (unsigned)W) \
                        ? X[nbOff[j] + cOff + iy * W + ix] : 0.f;             \
        }                                                                     \
    }

    aReg = aAct ? *reinterpret_cast<const float4*>(&At[(size_t)(kBegin + aRow) * BM + aCol])
                : make_float4(0.f, 0.f, 0.f, 0.f);
    C3X3_GATHER(kBegin);
    if (aAct) *reinterpret_cast<float4*>(&As[0][aRow][aCol]) = aReg;
#pragma unroll
    for (int j = 0; j < 4; j++) Bs[0][bRow][bCol + j] = bv[j];
    __syncthreads();

    int buf = 0;
    for (int k0 = kBegin + 8; k0 < kEnd; k0 += 8) {
        aReg = aAct ? *reinterpret_cast<const float4*>(&At[(size_t)(k0 + aRow) * BM + aCol])
                    : make_float4(0.f, 0.f, 0.f, 0.f);
        C3X3_GATHER(k0);
        GEMM_COMPUTE(buf);
        if (aAct) *reinterpret_cast<float4*>(&As[buf ^ 1][aRow][aCol]) = aReg;
#pragma unroll
        for (int j = 0; j < 4; j++) Bs[buf ^ 1][bRow][bCol + j] = bv[j];
        buf ^= 1;
        __syncthreads();
    }
    GEMM_COMPUTE(buf);
#undef C3X3_GATHER

    if (part) {
        float* p = part + (size_t)blockIdx.z * BM * N;
#pragma unroll
        for (int i = 0; i < TM; i++) {
            int m = ty * TM + i;
#pragma unroll
            for (int j = 0; j < 8; j += 4) {
                int n = nBase + tx * 8 + j;
                *reinterpret_cast<float4*>(&p[(size_t)m * N + n]) =
                    make_float4(acc[i][j], acc[i][j + 1], acc[i][j + 2], acc[i][j + 3]);
            }
        }
    } else {
        int bI[8], hwI[8];
#pragma unroll
        for (int j = 0; j < 8; j++) {
            int n = nBase + tx * 8 + j;
            bI[j] = n / HW; hwI[j] = n - bI[j] * HW;
        }
#pragma unroll
        for (int i = 0; i < TM; i++) {
            int m = ty * TM + i;
            if (m >= M) continue;
            float bvl = bias[m];
#pragma unroll
            for (int j = 0; j < 8; j++)
                Out[((size_t)(bI[j] * M + m)) * HW + hwI[j]] = acc[i][j] + bvl;
        }
    }
}

// ---- batched parity transposed-conv SGEMM: blockIdx.z = parity 0..3 ----
template<int BM, int TM>
__global__ __launch_bounds__(256) void sgemm_tconv(
        const float* __restrict__ AtAll, const float* __restrict__ X,
        const float* __restrict__ bias, float* __restrict__ Out,
        int O, int N, int H, int W) {
    __shared__ float As[2][8][BM];
    __shared__ float Bs[2][8][128];
    const int tid = threadIdx.x;
    const int p = blockIdx.z;
    const int ry = p >> 1, rx = p & 1;
    const int lnt = (p == 0) ? 0 : (p == 3) ? 2 : 1;
    const int ntm1 = (1 << lnt) - 1;
    const int K = O << lnt;
    const int OO = O * O;
    const float* At = AtAll + (size_t)OO * ((p == 0) ? 0 : (p == 1) ? 1 : (p == 2) ? 3 : 5);

    const int mBase = blockIdx.y * BM;
    const int nBase = blockIdx.x * 128;
    constexpr int TPR = BM / 4;
    const int aRow = tid / TPR;
    const int aCol = (tid % TPR) * 4;
    const bool aAct = (tid < 8 * TPR);
    const int bRow = tid >> 5, bCol = (tid & 31) << 2;
    const int ty = tid >> 4, tx = tid & 15;
    const int HW = H * W;

    int ny[4], nx[4];
    size_t nbOff[4];
#pragma unroll
    for (int j = 0; j < 4; j++) {
        int n = nBase + bCol + j;
        int b = n / HW;
        int hw = n - b * HW;
        ny[j] = hw / W; nx[j] = hw - ny[j] * W;
        nbOff[j] = (size_t)b * O * HW;
    }

    float acc[TM][8] = {};
    float4 aReg;
    float bv[4];

#define TC_GATHER(K0)                                                 \
    {                                                                 \
        int kr = (K0) + bRow;                                         \
        int c = kr >> lnt;                                            \
        int t = kr & ntm1;                                            \
        int tyi = t >> rx;                                            \
        int txi = t & rx;                                             \
        int dy = ry * (1 - tyi);                                      \
        int dx = rx * (1 - txi);                                      \
        size_t cOff = (size_t)c * HW;                                 \
        _Pragma("unroll")                                             \
        for (int j = 0; j < 4; j++) {                                 \
            int iy = ny[j] + dy, ix = nx[j] + dx;                     \
            bv[j] = (iy < H && ix < W)                                \
                        ? X[nbOff[j] + cOff + iy * W + ix] : 0.f;     \
        }                                                             \
    }

    aReg = aAct ? *reinterpret_cast<const float4*>(&At[(size_t)aRow * O + mBase + aCol])
                : make_float4(0.f, 0.f, 0.f, 0.f);
    TC_GATHER(0);
    if (aAct) *reinterpret_cast<float4*>(&As[0][aRow][aCol]) = aReg;
#pragma unroll
    for (int j = 0; j < 4; j++) Bs[0][bRow][bCol + j] = bv[j];
    __syncthreads();

    int buf = 0;
    for (int k0 = 8; k0 < K; k0 += 8) {
        aReg = aAct ? *reinterpret_cast<const float4*>(&At[(size_t)(k0 + aRow) * O + mBase + aCol])
                    : make_float4(0.f, 0.f, 0.f, 0.f);
        TC_GATHER(k0);
        GEMM_COMPUTE(buf);
        if (aAct) *reinterpret_cast<float4*>(&As[buf ^ 1][aRow][aCol]) = aReg;
#pragma unroll
        for (int j = 0; j < 4; j++) Bs[buf ^ 1][bRow][bCol + j] = bv[j];
        buf ^= 1;
        __syncthreads();
    }
    GEMM_COMPUTE(buf);
#undef TC_GATHER

    int bI[8], yI[8], xI[8];
#pragma unroll
    for (int j = 0; j < 8; j++) {
        int n = nBase + tx * 8 + j;
        int b = n / HW;
        int hw = n - b * HW;
        bI[j] = b; yI[j] = hw / W; xI[j] = hw - yI[j] * W;
    }
    int OH = 2 * H, OW = 2 * W;
#pragma unroll
    for (int i = 0; i < TM; i++) {
        int m = mBase + ty * TM + i;
        float bvl = bias[m];
#pragma unroll
        for (int j = 0; j < 8; j++) {
            int oy = 2 * yI[j] + ry;
            int ox = 2 * xI[j] + rx;
            Out[((size_t)(bI[j] * O + m) * OH + oy) * OW + ox] = acc[i][j] + bvl;
        }
    }
}

// ---------------------------------------------------------------------------
static inline float* symaddr(const void* sym) {
    void* p = nullptr;
    cudaGetSymbolAddress(&p, sym);
    return (float*)p;
}

extern "C" void kernel_launch(void* const* d_in, const int* in_sizes, int n_in,
                              void* d_out, int out_size) {
    float* col   = symaddr(g_col);
    float* bufA  = symaddr(g_bufA);
    float* bufB  = symaddr(g_bufB);
    float* omb   = symaddr(g_offmod);
    float* partb = symaddr(g_part);
    float* womT  = symaddr(g_womT);
    float* bom   = symaddr(g_bom);
    float* wT    = symaddr(g_wT);
    float* wtpT  = symaddr(g_wtpT);

    struct Stage {
        const float *w_off, *b_off, *w_mod, *b_mod, *w, *b, *wt, *bt;
        int C, H, W, O;
    };
    Stage st[3];
    for (int i = 0; i < 3; i++) {
        int base = 1 + i * 8;
        st[i].w_off = (const float*)d_in[base + 0];
        st[i].b_off = (const float*)d_in[base + 1];
        st[i].w_mod = (const float*)d_in[base + 2];
        st[i].b_mod = (const float*)d_in[base + 3];
        st[i].w     = (const float*)d_in[base + 4];
        st[i].b     = (const float*)d_in[base + 5];
        st[i].wt    = (const float*)d_in[base + 6];
        st[i].bt    = (const float*)d_in[base + 7];
    }
    st[0].C = 512; st[0].H = 32;  st[0].W = 32;  st[0].O = 256;
    st[1].C = 256; st[1].H = 64;  st[1].W = 64;  st[1].O = 128;
    st[2].C = 128; st[2].H = 128; st[2].W = 128; st[2].O = 64;

    // split-K configs per stage
    const int S_c3[3]  = {8, 2, 1};
    const int S_col[3] = {4, 2, 1};

    const float* X = (const float*)d_in[0];

    for (int i = 0; i < 3; i++) {
        int C = st[i].C, H = st[i].H, W = st[i].W, O = st[i].O;
        int HW = H * W;
        int N = BATCH * HW;
        int K9 = C * 9;

        // weight prep
        build_womT<<<(32 * K9 + 255) / 256, 256>>>(st[i].w_off, st[i].b_off,
                                                   st[i].w_mod, st[i].b_mod,
                                                   womT, bom, K9);
        transpose_w<<<(O * K9 + 255) / 256, 256>>>(st[i].w, wT, O, K9);
        build_wtpT<<<(9 * O * O + 255) / 256, 256>>>(st[i].wt, wtpT, O);

        // off/mod conv (fused im2col GEMM, M=27 pad 32)
        {
            int S = S_c3[i];
            if (S > 1) {
                sgemm_c3x3<32, 2><<<dim3(N / 128, 1, S), 256>>>(
                    womT, X, nullptr, nullptr, partb, 27, C, N, H, W, K9 / S);
                reduce_part<<<(27 * (N / 4) + 255) / 256, 256>>>(
                    partb, bom, omb, 27, 32, N, HW, S);
            } else {
                sgemm_c3x3<32, 2><<<dim3(N / 128, 1, 1), 256>>>(
                    womT, X, bom, omb, nullptr, 27, C, N, H, W, K9);
            }
        }

        // deformable im2col
        deform_im2col<<<(9 * N + 255) / 256, 256>>>(X, omb, col, C, H, W, N);

        // main deform conv GEMM
        float* Y = bufA;
        {
            int S = S_col[i];
            if (O >= 128) {
                if (S > 1) {
                    sgemm_col<128, 8><<<dim3(N / 128, O / 128, S), 256>>>(
                        wT, col, nullptr, nullptr, partb, O, N, HW, K9 / S);
                    reduce_part<<<(O * (N / 4) + 255) / 256, 256>>>(
                        partb, st[i].b, Y, O, O, N, HW, S);
                } else {
                    sgemm_col<128, 8><<<dim3(N / 128, O / 128, 1), 256>>>(
                        wT, col, st[i].b, Y, nullptr, O, N, HW, K9);
                }
            } else {
                sgemm_col<64, 4><<<dim3(N / 128, 1, 1), 256>>>(
                    wT, col, st[i].b, Y, nullptr, O, N, HW, K9);
            }
        }

        // parity-decomposed transposed conv: all 4 parities in one launch
        float* Xn = (i == 2) ? (float*)d_out : bufB;
        if (O >= 128)
            sgemm_tconv<128, 8><<<dim3(N / 128, O / 128, 4), 256>>>(
                wtpT, Y, st[i].bt, Xn, O, N, H, W);
        else
            sgemm_tconv<64, 4><<<dim3(N / 128, 1, 4), 256>>>(
                wtpT, Y, st[i].bt, Xn, O, N, H, W);

        X = Xn;
    }
}